// round 14
// baseline (speedup 1.0000x reference)
#include <cuda_runtime.h>
#include <math.h>

// Problem constants (dataset-fixed)
#define BN    1024          // bsz * n_atoms
#define NEE   80            // nE
#define NZ    100           // z in [1,100]
#define CAPP  40000         // P
#define SD    32            // scatter_dim
#define AD    128           // atom_dim
#define GH    256           // geom hidden
#define PH    128           // pair hidden
#define TABROWS (NZ*NZ*NEE) // 800000
#define H1S   260           // padded smem stride

typedef unsigned long long ull;

// -------- scratch (static device memory; no allocs; 16B-aligned) --------
__device__ __align__(16) float g_E1[101*PH];
__device__ __align__(16) float g_E2[101*PH];
__device__ __align__(16) float g_CE[NEE*PH];
__device__ __align__(16) float g_tab[(size_t)NZ*NZ*NEE*SD];  // 102.4 MB pair-MLP table
__device__ __align__(16) float g_HA[BN*GH];
__device__ __align__(16) float g_HB[BN*GH];
__device__ __align__(16) float g_geomO[CAPP*SD];
__device__ __align__(16) float g_cw[CAPP];
__device__ __align__(16) int   g_pairid[CAPP];
__device__ __align__(16) int   g_cnt[BN];
__device__ __align__(16) int   g_off[BN+2];
__device__ __align__(16) int   g_cur[BN];
__device__ __align__(16) int   g_order[CAPP];
__device__ __align__(16) float g_agg[BN*NEE*SD];

// silu via tanh.approx: sigmoid(x) = 0.5*(1+tanh(x/2)) -> 1 MUFU
__device__ __forceinline__ float silu_f(float x){
    float t;
    asm("tanh.approx.f32 %0, %1;" : "=f"(t) : "f"(0.5f*x));
    return x*(0.5f + 0.5f*t);
}
__device__ __forceinline__ int clampi(int v, int lo, int hi){
    return v < lo ? lo : (v > hi ? hi : v);
}

// ---- packed f32x2 helpers ----
__device__ __forceinline__ ull fma2(ull a, ull b, ull c){
    ull d; asm("fma.rn.f32x2 %0, %1, %2, %3;" : "=l"(d) : "l"(a), "l"(b), "l"(c)); return d;
}
__device__ __forceinline__ ull pack2(float x){
    ull d; asm("mov.b64 %0, {%1, %1};" : "=l"(d) : "f"(x)); return d;
}
__device__ __forceinline__ float2 unpack2(ull v){
    float2 r; asm("mov.b64 {%0, %1}, %2;" : "=f"(r.x), "=f"(r.y) : "l"(v)); return r;
}

// -------- K1a: pair-MLP layer1 factor projections --------
__global__ void k_pe_layer1(const float* __restrict__ zemb, const float* __restrict__ ef,
                            const float* __restrict__ W1, const float* __restrict__ b1){
    int row = blockIdx.x;
    int c = threadIdx.x;            // 128
    if (row < 101){
        float a = 0.f;
        #pragma unroll
        for (int d=0; d<32; d++) a += zemb[row*32+d] * W1[d*PH + c];
        g_E1[row*PH + c] = a;
    } else if (row < 202){
        int z = row - 101;
        float a = 0.f;
        #pragma unroll
        for (int d=0; d<32; d++) a += zemb[z*32+d] * W1[(32+d)*PH + c];
        g_E2[z*PH + c] = a;
    } else {
        int e = row - 202;
        float a = b1[c];
        #pragma unroll
        for (int d=0; d<32; d++) a += ef[e*32+d] * W1[(64+d)*PH + c];
        g_CE[e*PH + c] = a;
    }
}

// -------- K1b: HA = h_flat @ gW1[0:128], HB = h_flat @ gW1[128:256] --------
__global__ void k_hproj(const float* __restrict__ h_flat, const float* __restrict__ gW1){
    __shared__ float hs[8][AD];
    int side = blockIdx.y;
    int r0 = blockIdx.x * 8;
    int tid = threadIdx.x;          // 256
    for (int i = tid; i < 8*AD; i += 256)
        hs[i/AD][i%AD] = h_flat[(size_t)(r0 + i/AD)*AD + (i%AD)];
    __syncthreads();
    int c = tid;                    // 256 cols
    float acc[8];
    #pragma unroll
    for (int r=0;r<8;r++) acc[r] = 0.f;
    for (int d=0; d<AD; d++){
        float w = gW1[(size_t)(side*AD + d)*GH + c];
        #pragma unroll
        for (int r=0;r<8;r++) acc[r] += hs[r][d]*w;
    }
    float* dst = side ? g_HB : g_HA;
    #pragma unroll
    for (int r=0;r<8;r++) dst[(size_t)(r0+r)*GH + c] = acc[r];
}

// -------- bucketing --------
__global__ void k_zero(){
    int i = blockIdx.x*256 + threadIdx.x;
    if (i < BN) g_cnt[i] = 0;
}
__global__ void k_count(const int* __restrict__ center, const int* __restrict__ pj,
                        const int* __restrict__ pk, const int* __restrict__ z,
                        int P, int bn){
    int p = blockIdx.x*256 + threadIdx.x;
    if (p < P){
        int c = clampi(center[p], 0, bn-1);
        atomicAdd(&g_cnt[c], 1);
        int j = clampi(pj[p], 0, bn-1);
        int k = clampi(pk[p], 0, bn-1);
        int zj = clampi(z[j], 1, NZ);
        int zk = clampi(z[k], 1, NZ);
        g_pairid[p] = (zj-1)*NZ + (zk-1);
    }
}
__global__ void k_scan(){
    __shared__ int s[BN];
    int i = threadIdx.x;
    int myc = g_cnt[i];
    s[i] = myc;
    __syncthreads();
    for (int d=1; d<BN; d<<=1){
        int v = (i>=d) ? s[i-d] : 0;
        __syncthreads();
        s[i] += v;
        __syncthreads();
    }
    int excl = s[i] - myc;
    g_off[i] = excl;
    g_cur[i] = excl;
    if (i == BN-1) g_off[BN] = s[i];
}
__global__ void k_place(const int* __restrict__ center, int P, int bn){
    int p = blockIdx.x*256 + threadIdx.x;
    if (p < P){
        int c = clampi(center[p], 0, bn-1);
        int pos = atomicAdd(&g_cur[c], 1);
        if (pos >= 0 && pos < CAPP) g_order[pos] = p;
    }
}

// -------- K2: geometry MLP per path (tile of 32 paths / block, 256 threads) --------
__global__ void k_geom(const float* __restrict__ gW1, const float* __restrict__ gb1,
                       const float* __restrict__ gW2, const float* __restrict__ gb2,
                       const float* __restrict__ gW3, const float* __restrict__ gb3,
                       const int* __restrict__ pj_, const int* __restrict__ pk_,
                       const float* __restrict__ r0j, const float* __restrict__ r0k,
                       const float* __restrict__ rjk, const float* __restrict__ pcos_,
                       int P, int bn){
    extern __shared__ float sm[];
    float* rbfs = sm;                     // [32][96]
    float* h1s  = rbfs + 32*96;           // [32][H1S]
    float* h2s  = h1s + 32*H1S;           // [32][H1S]
    float* pcos = h2s + 32*H1S;           // [32]
    int* pj = (int*)(pcos + 32);          // [32]
    int* pk = pj + 32;                    // [32]

    int p0 = blockIdx.x * 32;
    int tid = threadIdx.x;

    if (tid < 32){
        int p = p0 + tid;
        int pp = (p < P) ? p : (P-1);
        pj[tid] = clampi(pj_[pp], 0, bn-1);
        pk[tid] = clampi(pk_[pp], 0, bn-1);
        pcos[tid] = pcos_[pp];
        float a = r0j[pp], b = r0k[pp], d = rjk[pp];
        const float k5 = 0.6283185307179586f;  // pi/5
        float wa = (a < 5.0f) ? 0.5f*(cosf(k5*a)+1.0f) : 0.0f;
        float wb = (b < 5.0f) ? 0.5f*(cosf(k5*b)+1.0f) : 0.0f;
        float wd = (d < 5.0f) ? 0.5f*(cosf(k5*d)+1.0f) : 0.0f;
        if (p < P) g_cw[p] = wa*wb*wd;
    }
    // RBF features for 3 distances per path
    {
        const float width = 5.0f/31.0f;
        const float coeff = -0.5f/(width*width);
        for (int idx = tid; idx < 32*96; idx += 256){
            int r = idx / 96, t = idx % 96;
            int p = p0 + r;
            int pp = (p < P) ? p : (P-1);
            float rr = (t < 32) ? r0j[pp] : (t < 64) ? r0k[pp] : rjk[pp];
            rr = fminf(rr, 5.0f);
            int i = t & 31;
            float cen = 5.0f * (float)i / 31.0f;
            float d = rr - cen;
            rbfs[r*96 + t] = __expf(coeff*d*d);
        }
    }
    __syncthreads();
    // layer1: each thread owns one output col; rbfs consumed in float4 chunks (LDS.128)
    {
        int c = tid;  // 256
        float acc[32];
        float wcos = gW1[(size_t)352*GH + c];
        float bb = gb1[c];
        #pragma unroll 8
        for (int r=0;r<32;r++)
            acc[r] = g_HA[(size_t)pj[r]*GH + c] + g_HB[(size_t)pk[r]*GH + c] + pcos[r]*wcos + bb;
        for (int t4=0;t4<24;t4++){
            float w0 = gW1[(size_t)(256+t4*4+0)*GH + c];
            float w1 = gW1[(size_t)(256+t4*4+1)*GH + c];
            float w2 = gW1[(size_t)(256+t4*4+2)*GH + c];
            float w3 = gW1[(size_t)(256+t4*4+3)*GH + c];
            #pragma unroll 8
            for (int r=0;r<32;r++){
                float4 rv = *(const float4*)&rbfs[r*96 + t4*4];
                acc[r] += rv.x*w0 + rv.y*w1 + rv.z*w2 + rv.w*w3;
            }
        }
        #pragma unroll 8
        for (int r=0;r<32;r++) h1s[r*H1S + c] = silu_f(acc[r]);
    }
    __syncthreads();
    // layer2: 8 rows x 4 cols per thread (4 rowgroups x 64 colgroups)
    {
        int rg = tid >> 6, cg = tid & 63;
        int rr = rg*8, c0 = cg*4;
        ull acc2[8][2];
        #pragma unroll
        for (int i=0;i<8;i++){ acc2[i][0]=0ULL; acc2[i][1]=0ULL; }
        #pragma unroll 4
        for (int k=0;k<GH;k++){
            ulonglong2 wv = *(const ulonglong2*)(gW2 + (size_t)k*GH + c0);
            #pragma unroll
            for (int i=0;i<8;i++){
                ull hh = pack2(h1s[(rr+i)*H1S + k]);
                acc2[i][0] = fma2(hh, wv.x, acc2[i][0]);
                acc2[i][1] = fma2(hh, wv.y, acc2[i][1]);
            }
        }
        #pragma unroll
        for (int i=0;i<8;i++){
            float2 v0 = unpack2(acc2[i][0]);
            float2 v1 = unpack2(acc2[i][1]);
            h2s[(rr+i)*H1S + c0 + 0] = silu_f(v0.x + gb2[c0+0]);
            h2s[(rr+i)*H1S + c0 + 1] = silu_f(v0.y + gb2[c0+1]);
            h2s[(rr+i)*H1S + c0 + 2] = silu_f(v1.x + gb2[c0+2]);
            h2s[(rr+i)*H1S + c0 + 3] = silu_f(v1.y + gb2[c0+3]);
        }
    }
    __syncthreads();
    // layer3: 1 row x 4 cols per thread, f32x2 packed
    {
        int r = tid >> 3;
        int c0 = (tid & 7) * 4;
        ull a2[2] = {0ULL, 0ULL};
        #pragma unroll 4
        for (int k=0;k<GH;k++){
            ulonglong2 wv = *(const ulonglong2*)(gW3 + (size_t)k*SD + c0);
            ull hh = pack2(h2s[r*H1S + k]);
            a2[0] = fma2(hh, wv.x, a2[0]);
            a2[1] = fma2(hh, wv.y, a2[1]);
        }
        int p = p0 + r;
        if (p < P){
            float2 v0 = unpack2(a2[0]);
            float2 v1 = unpack2(a2[1]);
            float4 o;
            o.x = v0.x+gb3[c0]; o.y = v0.y+gb3[c0+1];
            o.z = v1.x+gb3[c0+2]; o.w = v1.y+gb3[c0+3];
            *(float4*)(g_geomO + (size_t)p*SD + c0) = o;
        }
    }
}

// -------- K3: pair-element table — two col-half passes for 4 blocks/SM --------
__global__ __launch_bounds__(128, 4)
void k_pairtab(const float* __restrict__ W2, const float* __restrict__ b2,
               const float* __restrict__ W3, const float* __restrict__ b3){
    extern __shared__ float psm[];
    float* hs  = psm;              // [64][132]
    float* h2s = psm + 64*132;     // [64][132]
    __shared__ int s_e1[64], s_e2[64], s_ce[64];
    int tid = threadIdx.x;          // 128
    int row0 = blockIdx.x * 64;
    if (tid < 64){
        int row = row0 + tid;
        int pr = row / NEE;
        int e  = row - pr*NEE;
        int zj0 = pr / NZ;
        int zk0 = pr - zj0*NZ;
        s_e1[tid] = (zj0+1)*PH;
        s_e2[tid] = (zk0+1)*PH;
        s_ce[tid] = e*PH;
    }
    __syncthreads();
    // layer1: column c = tid, all 64 rows
    {
        int c = tid;
        #pragma unroll 4
        for (int lr=0; lr<64; lr++){
            float v = g_E1[s_e1[lr] + c] + g_E2[s_e2[lr] + c] + g_CE[s_ce[lr] + c];
            hs[lr*132 + c] = silu_f(v);
        }
    }
    __syncthreads();
    // layer2: 8 rows x 8 cols per thread, done as two 8x4 passes (halves acc regs)
    {
        int rg = tid >> 4, cg = tid & 15;
        int rr = rg*8, c0 = cg*8;
        #pragma unroll
        for (int half=0; half<2; half++){
            int ch = c0 + half*4;
            ull acc2[8][2];
            #pragma unroll
            for (int i=0;i<8;i++){ acc2[i][0]=0ULL; acc2[i][1]=0ULL; }
            for (int k4=0;k4<PH/4;k4++){
                float4 h4[8];
                #pragma unroll
                for (int i=0;i<8;i++)
                    h4[i] = *(const float4*)&hs[(rr+i)*132 + k4*4];
                #pragma unroll
                for (int kk=0;kk<4;kk++){
                    int k = k4*4+kk;
                    ulonglong2 wv = *(const ulonglong2*)(W2 + (size_t)k*PH + ch);
                    #pragma unroll
                    for (int i=0;i<8;i++){
                        const float* hp = (const float*)&h4[i];
                        ull hh = pack2(hp[kk]);
                        acc2[i][0] = fma2(hh, wv.x, acc2[i][0]);
                        acc2[i][1] = fma2(hh, wv.y, acc2[i][1]);
                    }
                }
            }
            #pragma unroll
            for (int i=0;i<8;i++){
                float2 v0 = unpack2(acc2[i][0]);
                float2 v1 = unpack2(acc2[i][1]);
                h2s[(rr+i)*132 + ch + 0] = silu_f(v0.x + b2[ch+0]);
                h2s[(rr+i)*132 + ch + 1] = silu_f(v0.y + b2[ch+1]);
                h2s[(rr+i)*132 + ch + 2] = silu_f(v1.x + b2[ch+2]);
                h2s[(rr+i)*132 + ch + 3] = silu_f(v1.y + b2[ch+3]);
            }
        }
    }
    __syncthreads();
    // layer3: 4 rows x 4 cols per thread, K=128, k-chunked
    {
        int r3 = (tid >> 3) * 4;        // 16 rowgroups
        int c3 = (tid & 7) * 4;         // 8 colgroups
        ull a2[4][2];
        #pragma unroll
        for (int i=0;i<4;i++){ a2[i][0]=0ULL; a2[i][1]=0ULL; }
        for (int k4=0;k4<PH/4;k4++){
            float4 h4[4];
            #pragma unroll
            for (int i=0;i<4;i++)
                h4[i] = *(const float4*)&h2s[(r3+i)*132 + k4*4];
            #pragma unroll
            for (int kk=0;kk<4;kk++){
                int k = k4*4+kk;
                ulonglong2 wv = *(const ulonglong2*)(W3 + (size_t)k*SD + c3);
                #pragma unroll
                for (int i=0;i<4;i++){
                    const float* hp = (const float*)&h4[i];
                    ull hh = pack2(hp[kk]);
                    a2[i][0] = fma2(hh, wv.x, a2[i][0]);
                    a2[i][1] = fma2(hh, wv.y, a2[i][1]);
                }
            }
        }
        #pragma unroll
        for (int i=0;i<4;i++){
            int row = row0 + r3 + i;
            float2 v0 = unpack2(a2[i][0]);
            float2 v1 = unpack2(a2[i][1]);
            float4 o;
            o.x = v0.x+b3[c3];   o.y = v0.y+b3[c3+1];
            o.z = v1.x+b3[c3+2]; o.w = v1.y+b3[c3+3];
            *(float4*)(g_tab + (size_t)row*SD + c3) = o;
        }
    }
}

// -------- K5: per-center aggregation (one block per center, deterministic order) --------
__global__ void k_agg(){
    __shared__ int idxs[1024];
    int c = blockIdx.x;
    int tid = threadIdx.x;          // 256
    int beg = g_off[c], end = g_off[c+1];
    int cnt = end - beg;
    if (cnt < 0) cnt = 0;
    if (cnt > 1024) cnt = 1024;
    for (int i = tid; i < cnt; i += 256) idxs[i] = g_order[beg + i];
    __syncthreads();
    if (tid == 0){
        for (int i=1;i<cnt;i++){
            int v = idxs[i]; int j = i-1;
            while (j >= 0 && idxs[j] > v){ idxs[j+1] = idxs[j]; j--; }
            idxs[j+1] = v;
        }
    }
    __syncthreads();
    float acc[10];
    #pragma unroll
    for (int u=0;u<10;u++) acc[u] = 0.f;
    float norm = 0.f;
    int lane = tid & 31;
    for (int i=0;i<cnt;i++){
        int p = idxs[i];
        float cw = g_cw[p];
        norm += cw;
        float gv = g_geomO[(size_t)p*SD + lane] * cw;
        const float* tp = g_tab + (size_t)g_pairid[p] * (NEE*SD);
        #pragma unroll
        for (int u=0;u<10;u++) acc[u] += gv * tp[tid + 256*u];
    }
    float scale = 1.0f / fmaxf(norm, 1e-8f);
    #pragma unroll
    for (int u=0;u<10;u++) g_agg[(size_t)c*(NEE*SD) + tid + 256*u] = acc[u]*scale;
}

// -------- K6: output MLP (81920 rows, 32->256->128) --------
__global__ void k_outmlp(const float* __restrict__ W1, const float* __restrict__ b1,
                         const float* __restrict__ W2, const float* __restrict__ b2,
                         float* __restrict__ out){
    extern __shared__ float sm[];
    float* ins = sm;                 // [64][36]
    float* hsm = sm + 64*36;         // [64][260]
    int tid = threadIdx.x;           // 256
    int r0 = blockIdx.x * 64;
    for (int i = tid; i < 64*32; i += 256){
        int r = i >> 5, cc = i & 31;
        ins[r*36 + cc] = g_agg[(size_t)(r0+r)*32 + cc];
    }
    __syncthreads();
    // layer1: 8 rows x 8 cols per thread, K=32, f32x2 packed
    {
        int rg = tid >> 5, cg = tid & 31;
        int rr = rg*8, c0 = cg*8;
        ull acc2[8][4];
        #pragma unroll
        for (int i=0;i<8;i++)
            #pragma unroll
            for (int j=0;j<4;j++) acc2[i][j] = 0ULL;
        #pragma unroll 4
        for (int k=0;k<SD;k++){
            const ulonglong2* wp = (const ulonglong2*)(W1 + (size_t)k*GH + c0);
            ulonglong2 wv0 = wp[0];
            ulonglong2 wv1 = wp[1];
            #pragma unroll
            for (int i=0;i<8;i++){
                ull hh = pack2(ins[(rr+i)*36 + k]);
                acc2[i][0] = fma2(hh, wv0.x, acc2[i][0]);
                acc2[i][1] = fma2(hh, wv0.y, acc2[i][1]);
                acc2[i][2] = fma2(hh, wv1.x, acc2[i][2]);
                acc2[i][3] = fma2(hh, wv1.y, acc2[i][3]);
            }
        }
        #pragma unroll
        for (int i=0;i<8;i++)
            #pragma unroll
            for (int j=0;j<4;j++){
                float2 v = unpack2(acc2[i][j]);
                hsm[(rr+i)*260 + c0 + 2*j]   = silu_f(v.x + b1[c0+2*j]);
                hsm[(rr+i)*260 + c0 + 2*j+1] = silu_f(v.y + b1[c0+2*j+1]);
            }
    }
    __syncthreads();
    // layer2: 4 rows x 8 cols per thread, K=256, f32x2 packed
    {
        int rg = tid >> 4, cg = tid & 15;
        int rr = rg*4, c0 = cg*8;
        ull acc2[4][4];
        #pragma unroll
        for (int i=0;i<4;i++)
            #pragma unroll
            for (int j=0;j<4;j++) acc2[i][j] = 0ULL;
        #pragma unroll 4
        for (int k=0;k<GH;k++){
            const ulonglong2* wp = (const ulonglong2*)(W2 + (size_t)k*128 + c0);
            ulonglong2 wv0 = wp[0];
            ulonglong2 wv1 = wp[1];
            #pragma unroll
            for (int i=0;i<4;i++){
                ull hh = pack2(hsm[(rr+i)*260 + k]);
                acc2[i][0] = fma2(hh, wv0.x, acc2[i][0]);
                acc2[i][1] = fma2(hh, wv0.y, acc2[i][1]);
                acc2[i][2] = fma2(hh, wv1.x, acc2[i][2]);
                acc2[i][3] = fma2(hh, wv1.y, acc2[i][3]);
            }
        }
        #pragma unroll
        for (int i=0;i<4;i++){
            int row = r0 + rr + i;
            float2 va = unpack2(acc2[i][0]);
            float2 vb = unpack2(acc2[i][1]);
            float2 vc = unpack2(acc2[i][2]);
            float2 vd = unpack2(acc2[i][3]);
            float4 o1, o2;
            o1.x = va.x+b2[c0];   o1.y = va.y+b2[c0+1];
            o1.z = vb.x+b2[c0+2]; o1.w = vb.y+b2[c0+3];
            o2.x = vc.x+b2[c0+4]; o2.y = vc.y+b2[c0+5];
            o2.z = vd.x+b2[c0+6]; o2.w = vd.y+b2[c0+7];
            *(float4*)(out + (size_t)row*128 + c0)     = o1;
            *(float4*)(out + (size_t)row*128 + c0 + 4) = o2;
        }
    }
}

// ==================== host ====================
// Confirmed layout: dict order with scalars at 10,11.
extern "C" void kernel_launch(void* const* d_in, const int* in_sizes, int n_in,
                              void* d_out, int out_size){
    const float* h_flat = (const float*)d_in[0];
    const int*   z_flat = (const int*)d_in[1];
    const float* e_feat = (const float*)d_in[2];
    const int*   p_cen  = (const int*)d_in[3];
    const int*   p_j    = (const int*)d_in[4];
    const int*   p_k    = (const int*)d_in[5];
    const float* p_r0j  = (const float*)d_in[6];
    const float* p_r0k  = (const float*)d_in[7];
    const float* p_rjk  = (const float*)d_in[8];
    const float* p_cos  = (const float*)d_in[9];
    const float* z_emb  = (const float*)d_in[12];
    const float* peW1 = (const float*)d_in[13];
    const float* peb1 = (const float*)d_in[14];
    const float* peW2 = (const float*)d_in[15];
    const float* peb2 = (const float*)d_in[16];
    const float* peW3 = (const float*)d_in[17];
    const float* peb3 = (const float*)d_in[18];
    const float* gW1  = (const float*)d_in[19];
    const float* gb1  = (const float*)d_in[20];
    const float* gW2  = (const float*)d_in[21];
    const float* gb2  = (const float*)d_in[22];
    const float* gW3  = (const float*)d_in[23];
    const float* gb3  = (const float*)d_in[24];
    const float* oW1  = (const float*)d_in[25];
    const float* ob1  = (const float*)d_in[26];
    const float* oW2  = (const float*)d_in[27];
    const float* ob2  = (const float*)d_in[28];
    float* out = (float*)d_out;

    int P  = in_sizes[3];
    int bn = in_sizes[0] / AD;
    int nE = in_sizes[2] / 32;
    if (P > CAPP) P = CAPP;
    if (bn > BN) bn = BN;
    if (nE > NEE) nE = NEE;

    const int smem_geom = (32*96 + 2*32*H1S + 32)*4 + 64*4;   // 79232 B
    const int smem_out  = (64*36 + 64*260)*4;                 // 75776 B
    const int smem_pair = 2*64*132*4;                         // 67584 B
    cudaFuncSetAttribute(k_geom,    cudaFuncAttributeMaxDynamicSharedMemorySize, smem_geom);
    cudaFuncSetAttribute(k_outmlp,  cudaFuncAttributeMaxDynamicSharedMemorySize, smem_out);
    cudaFuncSetAttribute(k_pairtab, cudaFuncAttributeMaxDynamicSharedMemorySize, smem_pair);

    // ncu captures MY launch index 3 -> pairtab there to verify occupancy fix
    k_pe_layer1<<<202 + nE, PH>>>(z_emb, e_feat, peW1, peb1);            // 0
    k_hproj<<<dim3(bn/8, 2), 256>>>(h_flat, gW1);                        // 1
    k_zero<<<(BN + 255)/256, 256>>>();                                   // 2
    k_pairtab<<<TABROWS/64, 128, smem_pair>>>(peW2, peb2, peW3, peb3);   // 3 <- profiled
    k_count<<<(P + 255)/256, 256>>>(p_cen, p_j, p_k, z_flat, P, bn);     // 4
    k_scan<<<1, BN>>>();                                                 // 5
    k_place<<<(P + 255)/256, 256>>>(p_cen, P, bn);                       // 6
    k_geom<<<(P + 31)/32, 256, smem_geom>>>(gW1, gb1, gW2, gb2, gW3, gb3,
                                            p_j, p_k, p_r0j, p_r0k, p_rjk, p_cos, P, bn); // 7
    k_agg<<<bn, 256>>>();                                                // 8
    k_outmlp<<<(bn*nE)/64, 256, smem_out>>>(oW1, ob1, oW2, ob2, out);    // 9
}

// round 15
// speedup vs baseline: 1.0662x; 1.0662x over previous
#include <cuda_runtime.h>
#include <math.h>

// Problem constants (dataset-fixed)
#define BN    1024          // bsz * n_atoms
#define NEE   80            // nE
#define NZ    100           // z in [1,100]
#define CAPP  40000         // P
#define SD    32            // scatter_dim
#define AD    128           // atom_dim
#define GH    256           // geom hidden
#define PH    128           // pair hidden
#define TABROWS (NZ*NZ*NEE) // 800000
#define H1S   260           // padded smem stride

typedef unsigned long long ull;

// -------- scratch (static device memory; no allocs; 16B-aligned) --------
__device__ __align__(16) float g_E1[101*PH];
__device__ __align__(16) float g_E2[101*PH];
__device__ __align__(16) float g_CE[NEE*PH];
__device__ __align__(16) float g_tab[(size_t)NZ*NZ*NEE*SD];  // 102.4 MB pair-MLP table
__device__ __align__(16) float g_HA[BN*GH];
__device__ __align__(16) float g_HB[BN*GH];
__device__ __align__(16) float g_geomO[CAPP*SD];
__device__ __align__(16) float g_cw[CAPP];
__device__ __align__(16) int   g_pairid[CAPP];
__device__ __align__(16) int   g_cnt[BN];
__device__ __align__(16) int   g_off[BN+2];
__device__ __align__(16) int   g_cur[BN];
__device__ __align__(16) int   g_order[CAPP];
__device__ __align__(16) float g_agg[BN*NEE*SD];

// silu via tanh.approx: sigmoid(x) = 0.5*(1+tanh(x/2)) -> 1 MUFU
__device__ __forceinline__ float silu_f(float x){
    float t;
    asm("tanh.approx.f32 %0, %1;" : "=f"(t) : "f"(0.5f*x));
    return x*(0.5f + 0.5f*t);
}
__device__ __forceinline__ int clampi(int v, int lo, int hi){
    return v < lo ? lo : (v > hi ? hi : v);
}

// ---- packed f32x2 helpers ----
__device__ __forceinline__ ull fma2(ull a, ull b, ull c){
    ull d; asm("fma.rn.f32x2 %0, %1, %2, %3;" : "=l"(d) : "l"(a), "l"(b), "l"(c)); return d;
}
__device__ __forceinline__ ull pack2(float x){
    ull d; asm("mov.b64 %0, {%1, %1};" : "=l"(d) : "f"(x)); return d;
}
__device__ __forceinline__ float2 unpack2(ull v){
    float2 r; asm("mov.b64 {%0, %1}, %2;" : "=f"(r.x), "=f"(r.y) : "l"(v)); return r;
}

// -------- K1a: pair-MLP layer1 factor projections --------
__global__ void k_pe_layer1(const float* __restrict__ zemb, const float* __restrict__ ef,
                            const float* __restrict__ W1, const float* __restrict__ b1){
    int row = blockIdx.x;
    int c = threadIdx.x;            // 128
    if (row < 101){
        float a = 0.f;
        #pragma unroll
        for (int d=0; d<32; d++) a += zemb[row*32+d] * W1[d*PH + c];
        g_E1[row*PH + c] = a;
    } else if (row < 202){
        int z = row - 101;
        float a = 0.f;
        #pragma unroll
        for (int d=0; d<32; d++) a += zemb[z*32+d] * W1[(32+d)*PH + c];
        g_E2[z*PH + c] = a;
    } else {
        int e = row - 202;
        float a = b1[c];
        #pragma unroll
        for (int d=0; d<32; d++) a += ef[e*32+d] * W1[(64+d)*PH + c];
        g_CE[e*PH + c] = a;
    }
}

// -------- K1b: HA = h_flat @ gW1[0:128], HB = h_flat @ gW1[128:256] --------
__global__ void k_hproj(const float* __restrict__ h_flat, const float* __restrict__ gW1){
    __shared__ float hs[8][AD];
    int side = blockIdx.y;
    int r0 = blockIdx.x * 8;
    int tid = threadIdx.x;          // 256
    for (int i = tid; i < 8*AD; i += 256)
        hs[i/AD][i%AD] = h_flat[(size_t)(r0 + i/AD)*AD + (i%AD)];
    __syncthreads();
    int c = tid;                    // 256 cols
    float acc[8];
    #pragma unroll
    for (int r=0;r<8;r++) acc[r] = 0.f;
    for (int d=0; d<AD; d++){
        float w = gW1[(size_t)(side*AD + d)*GH + c];
        #pragma unroll
        for (int r=0;r<8;r++) acc[r] += hs[r][d]*w;
    }
    float* dst = side ? g_HB : g_HA;
    #pragma unroll
    for (int r=0;r<8;r++) dst[(size_t)(r0+r)*GH + c] = acc[r];
}

// -------- bucketing --------
__global__ void k_zero(){
    int i = blockIdx.x*256 + threadIdx.x;
    if (i < BN) g_cnt[i] = 0;
}
__global__ void k_count(const int* __restrict__ center, const int* __restrict__ pj,
                        const int* __restrict__ pk, const int* __restrict__ z,
                        int P, int bn){
    int p = blockIdx.x*256 + threadIdx.x;
    if (p < P){
        int c = clampi(center[p], 0, bn-1);
        atomicAdd(&g_cnt[c], 1);
        int j = clampi(pj[p], 0, bn-1);
        int k = clampi(pk[p], 0, bn-1);
        int zj = clampi(z[j], 1, NZ);
        int zk = clampi(z[k], 1, NZ);
        g_pairid[p] = (zj-1)*NZ + (zk-1);
    }
}
__global__ void k_scan(){
    __shared__ int s[BN];
    int i = threadIdx.x;
    int myc = g_cnt[i];
    s[i] = myc;
    __syncthreads();
    for (int d=1; d<BN; d<<=1){
        int v = (i>=d) ? s[i-d] : 0;
        __syncthreads();
        s[i] += v;
        __syncthreads();
    }
    int excl = s[i] - myc;
    g_off[i] = excl;
    g_cur[i] = excl;
    if (i == BN-1) g_off[BN] = s[i];
}
__global__ void k_place(const int* __restrict__ center, int P, int bn){
    int p = blockIdx.x*256 + threadIdx.x;
    if (p < P){
        int c = clampi(center[p], 0, bn-1);
        int pos = atomicAdd(&g_cur[c], 1);
        if (pos >= 0 && pos < CAPP) g_order[pos] = p;
    }
}

// -------- K2: geometry MLP per path (tile of 32 paths / block, 256 threads) --------
__global__ void k_geom(const float* __restrict__ gW1, const float* __restrict__ gb1,
                       const float* __restrict__ gW2, const float* __restrict__ gb2,
                       const float* __restrict__ gW3, const float* __restrict__ gb3,
                       const int* __restrict__ pj_, const int* __restrict__ pk_,
                       const float* __restrict__ r0j, const float* __restrict__ r0k,
                       const float* __restrict__ rjk, const float* __restrict__ pcos_,
                       int P, int bn){
    extern __shared__ float sm[];
    float* rbfs = sm;                     // [32][96]
    float* h1s  = rbfs + 32*96;           // [32][H1S]
    float* h2s  = h1s + 32*H1S;           // [32][H1S]
    float* pcos = h2s + 32*H1S;           // [32]
    int* pj = (int*)(pcos + 32);          // [32]
    int* pk = pj + 32;                    // [32]

    int p0 = blockIdx.x * 32;
    int tid = threadIdx.x;

    if (tid < 32){
        int p = p0 + tid;
        int pp = (p < P) ? p : (P-1);
        pj[tid] = clampi(pj_[pp], 0, bn-1);
        pk[tid] = clampi(pk_[pp], 0, bn-1);
        pcos[tid] = pcos_[pp];
        float a = r0j[pp], b = r0k[pp], d = rjk[pp];
        const float k5 = 0.6283185307179586f;  // pi/5
        float wa = (a < 5.0f) ? 0.5f*(cosf(k5*a)+1.0f) : 0.0f;
        float wb = (b < 5.0f) ? 0.5f*(cosf(k5*b)+1.0f) : 0.0f;
        float wd = (d < 5.0f) ? 0.5f*(cosf(k5*d)+1.0f) : 0.0f;
        if (p < P) g_cw[p] = wa*wb*wd;
    }
    // RBF features for 3 distances per path
    {
        const float width = 5.0f/31.0f;
        const float coeff = -0.5f/(width*width);
        for (int idx = tid; idx < 32*96; idx += 256){
            int r = idx / 96, t = idx % 96;
            int p = p0 + r;
            int pp = (p < P) ? p : (P-1);
            float rr = (t < 32) ? r0j[pp] : (t < 64) ? r0k[pp] : rjk[pp];
            rr = fminf(rr, 5.0f);
            int i = t & 31;
            float cen = 5.0f * (float)i / 31.0f;
            float d = rr - cen;
            rbfs[r*96 + t] = __expf(coeff*d*d);
        }
    }
    __syncthreads();
    // layer1: each thread owns one output col for all 32 rows
    {
        int c = tid;  // 256
        float acc[32];
        float wcos = gW1[(size_t)352*GH + c];
        float bb = gb1[c];
        #pragma unroll 8
        for (int r=0;r<32;r++)
            acc[r] = g_HA[(size_t)pj[r]*GH + c] + g_HB[(size_t)pk[r]*GH + c] + pcos[r]*wcos + bb;
        for (int t=0;t<96;t++){
            float w = gW1[(size_t)(256+t)*GH + c];
            #pragma unroll
            for (int r=0;r<32;r++) acc[r] += rbfs[r*96+t]*w;
        }
        #pragma unroll 8
        for (int r=0;r<32;r++) h1s[r*H1S + c] = silu_f(acc[r]);
    }
    __syncthreads();
    // layer2: 4 rows x 8 cols per thread, f32x2 packed
    {
        int rg = tid >> 5, cg = tid & 31;
        int rr = rg*4, c0 = cg*8;
        ull acc2[4][4];
        #pragma unroll
        for (int i=0;i<4;i++)
            #pragma unroll
            for (int j=0;j<4;j++) acc2[i][j] = 0ULL;
        #pragma unroll 4
        for (int k=0;k<GH;k++){
            const ulonglong2* wp = (const ulonglong2*)(gW2 + (size_t)k*GH + c0);
            ulonglong2 wv0 = wp[0];
            ulonglong2 wv1 = wp[1];
            #pragma unroll
            for (int i=0;i<4;i++){
                ull hh = pack2(h1s[(rr+i)*H1S + k]);
                acc2[i][0] = fma2(hh, wv0.x, acc2[i][0]);
                acc2[i][1] = fma2(hh, wv0.y, acc2[i][1]);
                acc2[i][2] = fma2(hh, wv1.x, acc2[i][2]);
                acc2[i][3] = fma2(hh, wv1.y, acc2[i][3]);
            }
        }
        #pragma unroll
        for (int i=0;i<4;i++)
            #pragma unroll
            for (int j=0;j<4;j++){
                float2 v = unpack2(acc2[i][j]);
                h2s[(rr+i)*H1S + c0 + 2*j]   = silu_f(v.x + gb2[c0+2*j]);
                h2s[(rr+i)*H1S + c0 + 2*j+1] = silu_f(v.y + gb2[c0+2*j+1]);
            }
    }
    __syncthreads();
    // layer3: 1 row x 4 cols per thread, f32x2 packed
    {
        int r = tid >> 3;
        int c0 = (tid & 7) * 4;
        ull a2[2] = {0ULL, 0ULL};
        #pragma unroll 4
        for (int k=0;k<GH;k++){
            ulonglong2 wv = *(const ulonglong2*)(gW3 + (size_t)k*SD + c0);
            ull hh = pack2(h2s[r*H1S + k]);
            a2[0] = fma2(hh, wv.x, a2[0]);
            a2[1] = fma2(hh, wv.y, a2[1]);
        }
        int p = p0 + r;
        if (p < P){
            float2 v0 = unpack2(a2[0]);
            float2 v1 = unpack2(a2[1]);
            float4 o;
            o.x = v0.x+gb3[c0]; o.y = v0.y+gb3[c0+1];
            o.z = v1.x+gb3[c0+2]; o.w = v1.y+gb3[c0+3];
            *(float4*)(g_geomO + (size_t)p*SD + c0) = o;
        }
    }
}

// -------- K3: pair-element table — R11 version (float4 k-chunks, 8x8 tiles) --------
__global__ __launch_bounds__(128)
void k_pairtab(const float* __restrict__ W2, const float* __restrict__ b2,
               const float* __restrict__ W3, const float* __restrict__ b3){
    extern __shared__ float psm[];
    float* hs  = psm;              // [64][132]
    float* h2s = psm + 64*132;     // [64][132]
    __shared__ int s_e1[64], s_e2[64], s_ce[64];
    int tid = threadIdx.x;          // 128
    int row0 = blockIdx.x * 64;
    if (tid < 64){
        int row = row0 + tid;
        int pr = row / NEE;
        int e  = row - pr*NEE;
        int zj0 = pr / NZ;
        int zk0 = pr - zj0*NZ;
        s_e1[tid] = (zj0+1)*PH;
        s_e2[tid] = (zk0+1)*PH;
        s_ce[tid] = e*PH;
    }
    __syncthreads();
    // layer1: column c = tid, all 64 rows
    {
        int c = tid;
        #pragma unroll 4
        for (int lr=0; lr<64; lr++){
            float v = g_E1[s_e1[lr] + c] + g_E2[s_e2[lr] + c] + g_CE[s_ce[lr] + c];
            hs[lr*132 + c] = silu_f(v);
        }
    }
    __syncthreads();
    // layer2: 8 rows x 8 cols per thread, K=128, k-chunked float4 hs loads
    {
        int rg = tid >> 4, cg = tid & 15;
        int rr = rg*8, c0 = cg*8;
        ull acc2[8][4];
        #pragma unroll
        for (int i=0;i<8;i++)
            #pragma unroll
            for (int j=0;j<4;j++) acc2[i][j] = 0ULL;
        for (int k4=0;k4<PH/4;k4++){
            float4 h4[8];
            #pragma unroll
            for (int i=0;i<8;i++)
                h4[i] = *(const float4*)&hs[(rr+i)*132 + k4*4];
            #pragma unroll
            for (int kk=0;kk<4;kk++){
                int k = k4*4+kk;
                const ulonglong2* wp = (const ulonglong2*)(W2 + (size_t)k*PH + c0);
                ulonglong2 wv0 = wp[0];
                ulonglong2 wv1 = wp[1];
                #pragma unroll
                for (int i=0;i<8;i++){
                    const float* hp = (const float*)&h4[i];
                    ull hh = pack2(hp[kk]);
                    acc2[i][0] = fma2(hh, wv0.x, acc2[i][0]);
                    acc2[i][1] = fma2(hh, wv0.y, acc2[i][1]);
                    acc2[i][2] = fma2(hh, wv1.x, acc2[i][2]);
                    acc2[i][3] = fma2(hh, wv1.y, acc2[i][3]);
                }
            }
        }
        #pragma unroll
        for (int i=0;i<8;i++)
            #pragma unroll
            for (int j=0;j<4;j++){
                float2 v = unpack2(acc2[i][j]);
                h2s[(rr+i)*132 + c0 + 2*j]   = silu_f(v.x + b2[c0+2*j]);
                h2s[(rr+i)*132 + c0 + 2*j+1] = silu_f(v.y + b2[c0+2*j+1]);
            }
    }
    __syncthreads();
    // layer3: 4 rows x 4 cols per thread, K=128, k-chunked
    {
        int r3 = (tid >> 3) * 4;        // 16 rowgroups
        int c3 = (tid & 7) * 4;         // 8 colgroups
        ull a2[4][2];
        #pragma unroll
        for (int i=0;i<4;i++){ a2[i][0]=0ULL; a2[i][1]=0ULL; }
        for (int k4=0;k4<PH/4;k4++){
            float4 h4[4];
            #pragma unroll
            for (int i=0;i<4;i++)
                h4[i] = *(const float4*)&h2s[(r3+i)*132 + k4*4];
            #pragma unroll
            for (int kk=0;kk<4;kk++){
                int k = k4*4+kk;
                ulonglong2 wv = *(const ulonglong2*)(W3 + (size_t)k*SD + c3);
                #pragma unroll
                for (int i=0;i<4;i++){
                    const float* hp = (const float*)&h4[i];
                    ull hh = pack2(hp[kk]);
                    a2[i][0] = fma2(hh, wv.x, a2[i][0]);
                    a2[i][1] = fma2(hh, wv.y, a2[i][1]);
                }
            }
        }
        #pragma unroll
        for (int i=0;i<4;i++){
            int row = row0 + r3 + i;
            float2 v0 = unpack2(a2[i][0]);
            float2 v1 = unpack2(a2[i][1]);
            float4 o;
            o.x = v0.x+b3[c3];   o.y = v0.y+b3[c3+1];
            o.z = v1.x+b3[c3+2]; o.w = v1.y+b3[c3+3];
            *(float4*)(g_tab + (size_t)row*SD + c3) = o;
        }
    }
}

// -------- K5: per-center aggregation (one block per center, deterministic order) --------
__global__ void k_agg(){
    __shared__ int idxs[1024];
    int c = blockIdx.x;
    int tid = threadIdx.x;          // 256
    int beg = g_off[c], end = g_off[c+1];
    int cnt = end - beg;
    if (cnt < 0) cnt = 0;
    if (cnt > 1024) cnt = 1024;
    for (int i = tid; i < cnt; i += 256) idxs[i] = g_order[beg + i];
    __syncthreads();
    if (tid == 0){
        for (int i=1;i<cnt;i++){
            int v = idxs[i]; int j = i-1;
            while (j >= 0 && idxs[j] > v){ idxs[j+1] = idxs[j]; j--; }
            idxs[j+1] = v;
        }
    }
    __syncthreads();
    float acc[10];
    #pragma unroll
    for (int u=0;u<10;u++) acc[u] = 0.f;
    float norm = 0.f;
    int lane = tid & 31;
    for (int i=0;i<cnt;i++){
        int p = idxs[i];
        float cw = g_cw[p];
        norm += cw;
        float gv = g_geomO[(size_t)p*SD + lane] * cw;
        const float* tp = g_tab + (size_t)g_pairid[p] * (NEE*SD);
        #pragma unroll
        for (int u=0;u<10;u++) acc[u] += gv * tp[tid + 256*u];
    }
    float scale = 1.0f / fmaxf(norm, 1e-8f);
    #pragma unroll
    for (int u=0;u<10;u++) g_agg[(size_t)c*(NEE*SD) + tid + 256*u] = acc[u]*scale;
}

// -------- K6: output MLP (81920 rows, 32->256->128) --------
__global__ void k_outmlp(const float* __restrict__ W1, const float* __restrict__ b1,
                         const float* __restrict__ W2, const float* __restrict__ b2,
                         float* __restrict__ out){
    extern __shared__ float sm[];
    float* ins = sm;                 // [64][36]
    float* hsm = sm + 64*36;         // [64][260]
    int tid = threadIdx.x;           // 256
    int r0 = blockIdx.x * 64;
    for (int i = tid; i < 64*32; i += 256){
        int r = i >> 5, cc = i & 31;
        ins[r*36 + cc] = g_agg[(size_t)(r0+r)*32 + cc];
    }
    __syncthreads();
    // layer1: 8 rows x 8 cols per thread, K=32, f32x2 packed
    {
        int rg = tid >> 5, cg = tid & 31;
        int rr = rg*8, c0 = cg*8;
        ull acc2[8][4];
        #pragma unroll
        for (int i=0;i<8;i++)
            #pragma unroll
            for (int j=0;j<4;j++) acc2[i][j] = 0ULL;
        #pragma unroll 4
        for (int k=0;k<SD;k++){
            const ulonglong2* wp = (const ulonglong2*)(W1 + (size_t)k*GH + c0);
            ulonglong2 wv0 = wp[0];
            ulonglong2 wv1 = wp[1];
            #pragma unroll
            for (int i=0;i<8;i++){
                ull hh = pack2(ins[(rr+i)*36 + k]);
                acc2[i][0] = fma2(hh, wv0.x, acc2[i][0]);
                acc2[i][1] = fma2(hh, wv0.y, acc2[i][1]);
                acc2[i][2] = fma2(hh, wv1.x, acc2[i][2]);
                acc2[i][3] = fma2(hh, wv1.y, acc2[i][3]);
            }
        }
        #pragma unroll
        for (int i=0;i<8;i++)
            #pragma unroll
            for (int j=0;j<4;j++){
                float2 v = unpack2(acc2[i][j]);
                hsm[(rr+i)*260 + c0 + 2*j]   = silu_f(v.x + b1[c0+2*j]);
                hsm[(rr+i)*260 + c0 + 2*j+1] = silu_f(v.y + b1[c0+2*j+1]);
            }
    }
    __syncthreads();
    // layer2: 4 rows x 8 cols per thread, K=256, f32x2 packed
    {
        int rg = tid >> 4, cg = tid & 15;
        int rr = rg*4, c0 = cg*8;
        ull acc2[4][4];
        #pragma unroll
        for (int i=0;i<4;i++)
            #pragma unroll
            for (int j=0;j<4;j++) acc2[i][j] = 0ULL;
        #pragma unroll 4
        for (int k=0;k<GH;k++){
            const ulonglong2* wp = (const ulonglong2*)(W2 + (size_t)k*128 + c0);
            ulonglong2 wv0 = wp[0];
            ulonglong2 wv1 = wp[1];
            #pragma unroll
            for (int i=0;i<4;i++){
                ull hh = pack2(hsm[(rr+i)*260 + k]);
                acc2[i][0] = fma2(hh, wv0.x, acc2[i][0]);
                acc2[i][1] = fma2(hh, wv0.y, acc2[i][1]);
                acc2[i][2] = fma2(hh, wv1.x, acc2[i][2]);
                acc2[i][3] = fma2(hh, wv1.y, acc2[i][3]);
            }
        }
        #pragma unroll
        for (int i=0;i<4;i++){
            int row = r0 + rr + i;
            float2 va = unpack2(acc2[i][0]);
            float2 vb = unpack2(acc2[i][1]);
            float2 vc = unpack2(acc2[i][2]);
            float2 vd = unpack2(acc2[i][3]);
            float4 o1, o2;
            o1.x = va.x+b2[c0];   o1.y = va.y+b2[c0+1];
            o1.z = vb.x+b2[c0+2]; o1.w = vb.y+b2[c0+3];
            o2.x = vc.x+b2[c0+4]; o2.y = vc.y+b2[c0+5];
            o2.z = vd.x+b2[c0+6]; o2.w = vd.y+b2[c0+7];
            *(float4*)(out + (size_t)row*128 + c0)     = o1;
            *(float4*)(out + (size_t)row*128 + c0 + 4) = o2;
        }
    }
}

// ==================== host ====================
// Confirmed layout: dict order with scalars at 10,11.
// Multi-stream fork-join (graph-capturable): pairtab chain || geom chain || bucketing.
extern "C" void kernel_launch(void* const* d_in, const int* in_sizes, int n_in,
                              void* d_out, int out_size){
    const float* h_flat = (const float*)d_in[0];
    const int*   z_flat = (const int*)d_in[1];
    const float* e_feat = (const float*)d_in[2];
    const int*   p_cen  = (const int*)d_in[3];
    const int*   p_j    = (const int*)d_in[4];
    const int*   p_k    = (const int*)d_in[5];
    const float* p_r0j  = (const float*)d_in[6];
    const float* p_r0k  = (const float*)d_in[7];
    const float* p_rjk  = (const float*)d_in[8];
    const float* p_cos  = (const float*)d_in[9];
    const float* z_emb  = (const float*)d_in[12];
    const float* peW1 = (const float*)d_in[13];
    const float* peb1 = (const float*)d_in[14];
    const float* peW2 = (const float*)d_in[15];
    const float* peb2 = (const float*)d_in[16];
    const float* peW3 = (const float*)d_in[17];
    const float* peb3 = (const float*)d_in[18];
    const float* gW1  = (const float*)d_in[19];
    const float* gb1  = (const float*)d_in[20];
    const float* gW2  = (const float*)d_in[21];
    const float* gb2  = (const float*)d_in[22];
    const float* gW3  = (const float*)d_in[23];
    const float* gb3  = (const float*)d_in[24];
    const float* oW1  = (const float*)d_in[25];
    const float* ob1  = (const float*)d_in[26];
    const float* oW2  = (const float*)d_in[27];
    const float* ob2  = (const float*)d_in[28];
    float* out = (float*)d_out;

    int P  = in_sizes[3];
    int bn = in_sizes[0] / AD;
    int nE = in_sizes[2] / 32;
    if (P > CAPP) P = CAPP;
    if (bn > BN) bn = BN;
    if (nE > NEE) nE = NEE;

    const int smem_geom = (32*96 + 2*32*H1S + 32)*4 + 64*4;   // 79232 B
    const int smem_out  = (64*36 + 64*260)*4;                 // 75776 B
    const int smem_pair = 2*64*132*4;                         // 67584 B
    cudaFuncSetAttribute(k_geom,    cudaFuncAttributeMaxDynamicSharedMemorySize, smem_geom);
    cudaFuncSetAttribute(k_outmlp,  cudaFuncAttributeMaxDynamicSharedMemorySize, smem_out);
    cudaFuncSetAttribute(k_pairtab, cudaFuncAttributeMaxDynamicSharedMemorySize, smem_pair);

    // Side streams + events, created once on the first (uncaptured correctness) call.
    static cudaStream_t s1 = 0, s2 = 0;
    static cudaEvent_t evRoot = 0, evGeom = 0, evPlace = 0;
    if (!s1){
        cudaStreamCreateWithFlags(&s1, cudaStreamNonBlocking);
        cudaStreamCreateWithFlags(&s2, cudaStreamNonBlocking);
        cudaEventCreateWithFlags(&evRoot,  cudaEventDisableTiming);
        cudaEventCreateWithFlags(&evGeom,  cudaEventDisableTiming);
        cudaEventCreateWithFlags(&evPlace, cudaEventDisableTiming);
    }

    // fork
    cudaEventRecord(evRoot, 0);
    cudaStreamWaitEvent(s1, evRoot, 0);
    cudaStreamWaitEvent(s2, evRoot, 0);

    // chain A (default stream): pe_layer1 -> pairtab
    k_pe_layer1<<<202 + nE, PH>>>(z_emb, e_feat, peW1, peb1);
    k_pairtab<<<TABROWS/64, 128, smem_pair>>>(peW2, peb2, peW3, peb3);

    // chain B (s1): hproj -> geom
    k_hproj<<<dim3(bn/8, 2), 256, 0, s1>>>(h_flat, gW1);
    k_geom<<<(P + 31)/32, 256, smem_geom, s1>>>(gW1, gb1, gW2, gb2, gW3, gb3,
                                                p_j, p_k, p_r0j, p_r0k, p_rjk, p_cos, P, bn);
    cudaEventRecord(evGeom, s1);

    // chain C (s2): zero -> count -> scan -> place
    k_zero<<<(BN + 255)/256, 256, 0, s2>>>();
    k_count<<<(P + 255)/256, 256, 0, s2>>>(p_cen, p_j, p_k, z_flat, P, bn);
    k_scan<<<1, BN, 0, s2>>>();
    k_place<<<(P + 255)/256, 256, 0, s2>>>(p_cen, P, bn);
    cudaEventRecord(evPlace, s2);

    // join into default stream
    cudaStreamWaitEvent(0, evGeom, 0);
    cudaStreamWaitEvent(0, evPlace, 0);

    k_agg<<<bn, 256>>>();
    k_outmlp<<<(bn*nE)/64, 256, smem_out>>>(oW1, ob1, oW2, ob2, out);
}

// round 17
// speedup vs baseline: 1.3624x; 1.2778x over previous
#include <cuda_runtime.h>
#include <math.h>
#include <stdint.h>

// Problem constants (dataset-fixed)
#define BN    1024          // bsz * n_atoms
#define NEE   80            // nE
#define NZ    100           // z in [1,100]
#define CAPP  40000         // P
#define SD    32            // scatter_dim
#define AD    128           // atom_dim
#define GH    256           // geom hidden
#define PH    128           // pair hidden
#define TABROWS (NZ*NZ*NEE) // 800000
#define H1S   260           // padded smem stride

typedef unsigned long long ull;

// -------- scratch (static device memory; no allocs; 16B-aligned) --------
__device__ __align__(16) float g_E1[101*PH];
__device__ __align__(16) float g_E2[101*PH];
__device__ __align__(16) float g_CE[NEE*PH];
__device__ __align__(16) float g_tab[(size_t)NZ*NZ*NEE*SD];  // 102.4 MB pair-MLP table
__device__ __align__(16) float g_HA[BN*GH];
__device__ __align__(16) float g_HB[BN*GH];
__device__ __align__(16) float g_geomO[CAPP*SD];
__device__ __align__(16) float g_cw[CAPP];
__device__ __align__(16) int   g_pairid[CAPP];
__device__ __align__(16) int   g_cnt[BN];
__device__ __align__(16) int   g_off[BN+2];
__device__ __align__(16) int   g_cur[BN];
__device__ __align__(16) int   g_order[CAPP];
__device__ __align__(16) float g_agg[BN*NEE*SD];

// silu via tanh.approx: sigmoid(x) = 0.5*(1+tanh(x/2)) -> 1 MUFU
__device__ __forceinline__ float silu_f(float x){
    float t;
    asm("tanh.approx.f32 %0, %1;" : "=f"(t) : "f"(0.5f*x));
    return x*(0.5f + 0.5f*t);
}
__device__ __forceinline__ int clampi(int v, int lo, int hi){
    return v < lo ? lo : (v > hi ? hi : v);
}

// ---- packed f32x2 helpers ----
__device__ __forceinline__ ull fma2(ull a, ull b, ull c){
    ull d; asm("fma.rn.f32x2 %0, %1, %2, %3;" : "=l"(d) : "l"(a), "l"(b), "l"(c)); return d;
}
__device__ __forceinline__ ull pack2(float x){
    ull d; asm("mov.b64 %0, {%1, %1};" : "=l"(d) : "f"(x)); return d;
}
__device__ __forceinline__ float2 unpack2(ull v){
    float2 r; asm("mov.b64 {%0, %1}, %2;" : "=f"(r.x), "=f"(r.y) : "l"(v)); return r;
}

// ---- tf32 mma helpers ----
__device__ __forceinline__ uint32_t f2tf32(float x){
    uint32_t r; asm("cvt.rna.tf32.f32 %0, %1;" : "=r"(r) : "f"(x)); return r;
}
__device__ __forceinline__ void mma_tf32(float* c, const uint32_t* a, uint32_t b0, uint32_t b1){
    asm volatile("mma.sync.aligned.m16n8k8.row.col.f32.tf32.tf32.f32 "
        "{%0,%1,%2,%3}, {%4,%5,%6,%7}, {%8,%9}, {%0,%1,%2,%3};"
        : "+f"(c[0]), "+f"(c[1]), "+f"(c[2]), "+f"(c[3])
        : "r"(a[0]), "r"(a[1]), "r"(a[2]), "r"(a[3]), "r"(b0), "r"(b1));
}

// -------- K1a: pair-MLP layer1 factor projections --------
__global__ void k_pe_layer1(const float* __restrict__ zemb, const float* __restrict__ ef,
                            const float* __restrict__ W1, const float* __restrict__ b1){
    int row = blockIdx.x;
    int c = threadIdx.x;            // 128
    if (row < 101){
        float a = 0.f;
        #pragma unroll
        for (int d=0; d<32; d++) a += zemb[row*32+d] * W1[d*PH + c];
        g_E1[row*PH + c] = a;
    } else if (row < 202){
        int z = row - 101;
        float a = 0.f;
        #pragma unroll
        for (int d=0; d<32; d++) a += zemb[z*32+d] * W1[(32+d)*PH + c];
        g_E2[z*PH + c] = a;
    } else {
        int e = row - 202;
        float a = b1[c];
        #pragma unroll
        for (int d=0; d<32; d++) a += ef[e*32+d] * W1[(64+d)*PH + c];
        g_CE[e*PH + c] = a;
    }
}

// -------- K1b: HA = h_flat @ gW1[0:128], HB = h_flat @ gW1[128:256] --------
__global__ void k_hproj(const float* __restrict__ h_flat, const float* __restrict__ gW1){
    __shared__ float hs[8][AD];
    int side = blockIdx.y;
    int r0 = blockIdx.x * 8;
    int tid = threadIdx.x;          // 256
    for (int i = tid; i < 8*AD; i += 256)
        hs[i/AD][i%AD] = h_flat[(size_t)(r0 + i/AD)*AD + (i%AD)];
    __syncthreads();
    int c = tid;                    // 256 cols
    float acc[8];
    #pragma unroll
    for (int r=0;r<8;r++) acc[r] = 0.f;
    for (int d=0; d<AD; d++){
        float w = gW1[(size_t)(side*AD + d)*GH + c];
        #pragma unroll
        for (int r=0;r<8;r++) acc[r] += hs[r][d]*w;
    }
    float* dst = side ? g_HB : g_HA;
    #pragma unroll
    for (int r=0;r<8;r++) dst[(size_t)(r0+r)*GH + c] = acc[r];
}

// -------- bucketing --------
__global__ void k_zero(){
    int i = blockIdx.x*256 + threadIdx.x;
    if (i < BN) g_cnt[i] = 0;
}
__global__ void k_count(const int* __restrict__ center, const int* __restrict__ pj,
                        const int* __restrict__ pk, const int* __restrict__ z,
                        int P, int bn){
    int p = blockIdx.x*256 + threadIdx.x;
    if (p < P){
        int c = clampi(center[p], 0, bn-1);
        atomicAdd(&g_cnt[c], 1);
        int j = clampi(pj[p], 0, bn-1);
        int k = clampi(pk[p], 0, bn-1);
        int zj = clampi(z[j], 1, NZ);
        int zk = clampi(z[k], 1, NZ);
        g_pairid[p] = (zj-1)*NZ + (zk-1);
    }
}
__global__ void k_scan(){
    __shared__ int s[BN];
    int i = threadIdx.x;
    int myc = g_cnt[i];
    s[i] = myc;
    __syncthreads();
    for (int d=1; d<BN; d<<=1){
        int v = (i>=d) ? s[i-d] : 0;
        __syncthreads();
        s[i] += v;
        __syncthreads();
    }
    int excl = s[i] - myc;
    g_off[i] = excl;
    g_cur[i] = excl;
    if (i == BN-1) g_off[BN] = s[i];
}
__global__ void k_place(const int* __restrict__ center, int P, int bn){
    int p = blockIdx.x*256 + threadIdx.x;
    if (p < P){
        int c = clampi(center[p], 0, bn-1);
        int pos = atomicAdd(&g_cur[c], 1);
        if (pos >= 0 && pos < CAPP) g_order[pos] = p;
    }
}

// -------- K2: geometry MLP per path (tile of 32 paths / block, 256 threads) --------
__global__ void k_geom(const float* __restrict__ gW1, const float* __restrict__ gb1,
                       const float* __restrict__ gW2, const float* __restrict__ gb2,
                       const float* __restrict__ gW3, const float* __restrict__ gb3,
                       const int* __restrict__ pj_, const int* __restrict__ pk_,
                       const float* __restrict__ r0j, const float* __restrict__ r0k,
                       const float* __restrict__ rjk, const float* __restrict__ pcos_,
                       int P, int bn){
    extern __shared__ float sm[];
    float* rbfs = sm;                     // [32][96]
    float* h1s  = rbfs + 32*96;           // [32][H1S]
    float* h2s  = h1s + 32*H1S;           // [32][H1S]
    float* pcos = h2s + 32*H1S;           // [32]
    int* pj = (int*)(pcos + 32);          // [32]
    int* pk = pj + 32;                    // [32]

    int p0 = blockIdx.x * 32;
    int tid = threadIdx.x;

    if (tid < 32){
        int p = p0 + tid;
        int pp = (p < P) ? p : (P-1);
        pj[tid] = clampi(pj_[pp], 0, bn-1);
        pk[tid] = clampi(pk_[pp], 0, bn-1);
        pcos[tid] = pcos_[pp];
        float a = r0j[pp], b = r0k[pp], d = rjk[pp];
        const float k5 = 0.6283185307179586f;  // pi/5
        float wa = (a < 5.0f) ? 0.5f*(cosf(k5*a)+1.0f) : 0.0f;
        float wb = (b < 5.0f) ? 0.5f*(cosf(k5*b)+1.0f) : 0.0f;
        float wd = (d < 5.0f) ? 0.5f*(cosf(k5*d)+1.0f) : 0.0f;
        if (p < P) g_cw[p] = wa*wb*wd;
    }
    // RBF features for 3 distances per path
    {
        const float width = 5.0f/31.0f;
        const float coeff = -0.5f/(width*width);
        for (int idx = tid; idx < 32*96; idx += 256){
            int r = idx / 96, t = idx % 96;
            int p = p0 + r;
            int pp = (p < P) ? p : (P-1);
            float rr = (t < 32) ? r0j[pp] : (t < 64) ? r0k[pp] : rjk[pp];
            rr = fminf(rr, 5.0f);
            int i = t & 31;
            float cen = 5.0f * (float)i / 31.0f;
            float d = rr - cen;
            rbfs[r*96 + t] = __expf(coeff*d*d);
        }
    }
    __syncthreads();
    // layer1: each thread owns one output col for all 32 rows
    {
        int c = tid;  // 256
        float acc[32];
        float wcos = gW1[(size_t)352*GH + c];
        float bb = gb1[c];
        #pragma unroll 8
        for (int r=0;r<32;r++)
            acc[r] = g_HA[(size_t)pj[r]*GH + c] + g_HB[(size_t)pk[r]*GH + c] + pcos[r]*wcos + bb;
        for (int t=0;t<96;t++){
            float w = gW1[(size_t)(256+t)*GH + c];
            #pragma unroll
            for (int r=0;r<32;r++) acc[r] += rbfs[r*96+t]*w;
        }
        #pragma unroll 8
        for (int r=0;r<32;r++) h1s[r*H1S + c] = silu_f(acc[r]);
    }
    __syncthreads();
    // layer2: 4 rows x 8 cols per thread, f32x2 packed
    {
        int rg = tid >> 5, cg = tid & 31;
        int rr = rg*4, c0 = cg*8;
        ull acc2[4][4];
        #pragma unroll
        for (int i=0;i<4;i++)
            #pragma unroll
            for (int j=0;j<4;j++) acc2[i][j] = 0ULL;
        #pragma unroll 4
        for (int k=0;k<GH;k++){
            const ulonglong2* wp = (const ulonglong2*)(gW2 + (size_t)k*GH + c0);
            ulonglong2 wv0 = wp[0];
            ulonglong2 wv1 = wp[1];
            #pragma unroll
            for (int i=0;i<4;i++){
                ull hh = pack2(h1s[(rr+i)*H1S + k]);
                acc2[i][0] = fma2(hh, wv0.x, acc2[i][0]);
                acc2[i][1] = fma2(hh, wv0.y, acc2[i][1]);
                acc2[i][2] = fma2(hh, wv1.x, acc2[i][2]);
                acc2[i][3] = fma2(hh, wv1.y, acc2[i][3]);
            }
        }
        #pragma unroll
        for (int i=0;i<4;i++)
            #pragma unroll
            for (int j=0;j<4;j++){
                float2 v = unpack2(acc2[i][j]);
                h2s[(rr+i)*H1S + c0 + 2*j]   = silu_f(v.x + gb2[c0+2*j]);
                h2s[(rr+i)*H1S + c0 + 2*j+1] = silu_f(v.y + gb2[c0+2*j+1]);
            }
    }
    __syncthreads();
    // layer3: 1 row x 4 cols per thread, f32x2 packed
    {
        int r = tid >> 3;
        int c0 = (tid & 7) * 4;
        ull a2[2] = {0ULL, 0ULL};
        #pragma unroll 4
        for (int k=0;k<GH;k++){
            ulonglong2 wv = *(const ulonglong2*)(gW3 + (size_t)k*SD + c0);
            ull hh = pack2(h2s[r*H1S + k]);
            a2[0] = fma2(hh, wv.x, a2[0]);
            a2[1] = fma2(hh, wv.y, a2[1]);
        }
        int p = p0 + r;
        if (p < P){
            float2 v0 = unpack2(a2[0]);
            float2 v1 = unpack2(a2[1]);
            float4 o;
            o.x = v0.x+gb3[c0]; o.y = v0.y+gb3[c0+1];
            o.z = v1.x+gb3[c0+2]; o.w = v1.y+gb3[c0+3];
            *(float4*)(g_geomO + (size_t)p*SD + c0) = o;
        }
    }
}

// -------- K3: pair-element table — tf32 tensor-core layers 2+3 --------
// 128 threads (4 warps), 64 rows/block. Layer1 fp32 -> hs. Layer2/3 mma.sync tf32.
__global__ __launch_bounds__(128)
void k_pairtab(const float* __restrict__ W2, const float* __restrict__ b2,
               const float* __restrict__ W3, const float* __restrict__ b3){
    extern __shared__ float psm[];
    float* hs  = psm;              // [64][132]
    float* h2s = psm + 64*132;     // [64][132]
    __shared__ int s_e1[64], s_e2[64], s_ce[64];
    int tid = threadIdx.x;          // 128
    int row0 = blockIdx.x * 64;
    if (tid < 64){
        int row = row0 + tid;
        int pr = row / NEE;
        int e  = row - pr*NEE;
        int zj0 = pr / NZ;
        int zk0 = pr - zj0*NZ;
        s_e1[tid] = (zj0+1)*PH;
        s_e2[tid] = (zk0+1)*PH;
        s_ce[tid] = e*PH;
    }
    __syncthreads();
    // layer1: column c = tid, all 64 rows (fp32)
    {
        int c = tid;
        #pragma unroll 4
        for (int lr=0; lr<64; lr++){
            float v = g_E1[s_e1[lr] + c] + g_E2[s_e2[lr] + c] + g_CE[s_ce[lr] + c];
            hs[lr*132 + c] = silu_f(v);
        }
    }
    __syncthreads();

    int warp = tid >> 5;
    int lane = tid & 31;
    int gid  = lane >> 2;     // 0..7
    int tig  = lane & 3;      // 0..3

    // layer2: C[64][128] = hs @ W2. Warp owns n-range [warp*32, warp*32+32).
    {
        int n0w = warp * 32;
        float acc[4][4][4];
        #pragma unroll
        for (int m=0;m<4;m++)
            #pragma unroll
            for (int n=0;n<4;n++){
                acc[m][n][0]=0.f; acc[m][n][1]=0.f; acc[m][n][2]=0.f; acc[m][n][3]=0.f;
            }
        for (int k0=0;k0<PH;k0+=8){
            uint32_t a[4][4];
            #pragma unroll
            for (int m=0;m<4;m++){
                int r = m*16;
                a[m][0] = f2tf32(hs[(r+gid)*132   + k0+tig]);
                a[m][1] = f2tf32(hs[(r+gid+8)*132 + k0+tig]);
                a[m][2] = f2tf32(hs[(r+gid)*132   + k0+tig+4]);
                a[m][3] = f2tf32(hs[(r+gid+8)*132 + k0+tig+4]);
            }
            uint32_t b[4][2];
            #pragma unroll
            for (int n=0;n<4;n++){
                int c = n0w + n*8 + gid;
                b[n][0] = f2tf32(W2[(size_t)(k0+tig)*PH   + c]);
                b[n][1] = f2tf32(W2[(size_t)(k0+tig+4)*PH + c]);
            }
            #pragma unroll
            for (int m=0;m<4;m++)
                #pragma unroll
                for (int n=0;n<4;n++)
                    mma_tf32(acc[m][n], a[m], b[n][0], b[n][1]);
        }
        #pragma unroll
        for (int m=0;m<4;m++)
            #pragma unroll
            for (int n=0;n<4;n++){
                int col = n0w + n*8 + 2*tig;
                int r = m*16;
                h2s[(r+gid)*132   + col]   = silu_f(acc[m][n][0] + b2[col]);
                h2s[(r+gid)*132   + col+1] = silu_f(acc[m][n][1] + b2[col+1]);
                h2s[(r+gid+8)*132 + col]   = silu_f(acc[m][n][2] + b2[col]);
                h2s[(r+gid+8)*132 + col+1] = silu_f(acc[m][n][3] + b2[col+1]);
            }
    }
    __syncthreads();
    // layer3: C[64][32] = h2s @ W3. Warp owns one n8 tile: n0 = warp*8.
    {
        int n0 = warp * 8;
        float acc[4][4];
        #pragma unroll
        for (int m=0;m<4;m++){ acc[m][0]=0.f; acc[m][1]=0.f; acc[m][2]=0.f; acc[m][3]=0.f; }
        for (int k0=0;k0<PH;k0+=8){
            uint32_t a[4][4];
            #pragma unroll
            for (int m=0;m<4;m++){
                int r = m*16;
                a[m][0] = f2tf32(h2s[(r+gid)*132   + k0+tig]);
                a[m][1] = f2tf32(h2s[(r+gid+8)*132 + k0+tig]);
                a[m][2] = f2tf32(h2s[(r+gid)*132   + k0+tig+4]);
                a[m][3] = f2tf32(h2s[(r+gid+8)*132 + k0+tig+4]);
            }
            uint32_t b0 = f2tf32(W3[(size_t)(k0+tig)*SD   + n0+gid]);
            uint32_t b1 = f2tf32(W3[(size_t)(k0+tig+4)*SD + n0+gid]);
            #pragma unroll
            for (int m=0;m<4;m++)
                mma_tf32(acc[m], a[m], b0, b1);
        }
        int col = n0 + 2*tig;
        #pragma unroll
        for (int m=0;m<4;m++){
            int r = row0 + m*16;
            float2 v0; v0.x = acc[m][0] + b3[col]; v0.y = acc[m][1] + b3[col+1];
            float2 v1; v1.x = acc[m][2] + b3[col]; v1.y = acc[m][3] + b3[col+1];
            *(float2*)&g_tab[(size_t)(r+gid)*SD   + col] = v0;
            *(float2*)&g_tab[(size_t)(r+gid+8)*SD + col] = v1;
        }
    }
}

// -------- K5: per-center aggregation (one block per center, deterministic order) --------
__global__ void k_agg(){
    __shared__ int idxs[1024];
    int c = blockIdx.x;
    int tid = threadIdx.x;          // 256
    int beg = g_off[c], end = g_off[c+1];
    int cnt = end - beg;
    if (cnt < 0) cnt = 0;
    if (cnt > 1024) cnt = 1024;
    for (int i = tid; i < cnt; i += 256) idxs[i] = g_order[beg + i];
    __syncthreads();
    if (tid == 0){
        for (int i=1;i<cnt;i++){
            int v = idxs[i]; int j = i-1;
            while (j >= 0 && idxs[j] > v){ idxs[j+1] = idxs[j]; j--; }
            idxs[j+1] = v;
        }
    }
    __syncthreads();
    float acc[10];
    #pragma unroll
    for (int u=0;u<10;u++) acc[u] = 0.f;
    float norm = 0.f;
    int lane = tid & 31;
    for (int i=0;i<cnt;i++){
        int p = idxs[i];
        float cw = g_cw[p];
        norm += cw;
        float gv = g_geomO[(size_t)p*SD + lane] * cw;
        const float* tp = g_tab + (size_t)g_pairid[p] * (NEE*SD);
        #pragma unroll
        for (int u=0;u<10;u++) acc[u] += gv * tp[tid + 256*u];
    }
    float scale = 1.0f / fmaxf(norm, 1e-8f);
    #pragma unroll
    for (int u=0;u<10;u++) g_agg[(size_t)c*(NEE*SD) + tid + 256*u] = acc[u]*scale;
}

// -------- K6: output MLP (81920 rows, 32->256->128) --------
__global__ void k_outmlp(const float* __restrict__ W1, const float* __restrict__ b1,
                         const float* __restrict__ W2, const float* __restrict__ b2,
                         float* __restrict__ out){
    extern __shared__ float sm[];
    float* ins = sm;                 // [64][36]
    float* hsm = sm + 64*36;         // [64][260]
    int tid = threadIdx.x;           // 256
    int r0 = blockIdx.x * 64;
    for (int i = tid; i < 64*32; i += 256){
        int r = i >> 5, cc = i & 31;
        ins[r*36 + cc] = g_agg[(size_t)(r0+r)*32 + cc];
    }
    __syncthreads();
    // layer1: 8 rows x 8 cols per thread, K=32, f32x2 packed
    {
        int rg = tid >> 5, cg = tid & 31;
        int rr = rg*8, c0 = cg*8;
        ull acc2[8][4];
        #pragma unroll
        for (int i=0;i<8;i++)
            #pragma unroll
            for (int j=0;j<4;j++) acc2[i][j] = 0ULL;
        #pragma unroll 4
        for (int k=0;k<SD;k++){
            const ulonglong2* wp = (const ulonglong2*)(W1 + (size_t)k*GH + c0);
            ulonglong2 wv0 = wp[0];
            ulonglong2 wv1 = wp[1];
            #pragma unroll
            for (int i=0;i<8;i++){
                ull hh = pack2(ins[(rr+i)*36 + k]);
                acc2[i][0] = fma2(hh, wv0.x, acc2[i][0]);
                acc2[i][1] = fma2(hh, wv0.y, acc2[i][1]);
                acc2[i][2] = fma2(hh, wv1.x, acc2[i][2]);
                acc2[i][3] = fma2(hh, wv1.y, acc2[i][3]);
            }
        }
        #pragma unroll
        for (int i=0;i<8;i++)
            #pragma unroll
            for (int j=0;j<4;j++){
                float2 v = unpack2(acc2[i][j]);
                hsm[(rr+i)*260 + c0 + 2*j]   = silu_f(v.x + b1[c0+2*j]);
                hsm[(rr+i)*260 + c0 + 2*j+1] = silu_f(v.y + b1[c0+2*j+1]);
            }
    }
    __syncthreads();
    // layer2: 4 rows x 8 cols per thread, K=256, f32x2 packed
    {
        int rg = tid >> 4, cg = tid & 15;
        int rr = rg*4, c0 = cg*8;
        ull acc2[4][4];
        #pragma unroll
        for (int i=0;i<4;i++)
            #pragma unroll
            for (int j=0;j<4;j++) acc2[i][j] = 0ULL;
        #pragma unroll 4
        for (int k=0;k<GH;k++){
            const ulonglong2* wp = (const ulonglong2*)(W2 + (size_t)k*128 + c0);
            ulonglong2 wv0 = wp[0];
            ulonglong2 wv1 = wp[1];
            #pragma unroll
            for (int i=0;i<4;i++){
                ull hh = pack2(hsm[(rr+i)*260 + k]);
                acc2[i][0] = fma2(hh, wv0.x, acc2[i][0]);
                acc2[i][1] = fma2(hh, wv0.y, acc2[i][1]);
                acc2[i][2] = fma2(hh, wv1.x, acc2[i][2]);
                acc2[i][3] = fma2(hh, wv1.y, acc2[i][3]);
            }
        }
        #pragma unroll
        for (int i=0;i<4;i++){
            int row = r0 + rr + i;
            float2 va = unpack2(acc2[i][0]);
            float2 vb = unpack2(acc2[i][1]);
            float2 vc = unpack2(acc2[i][2]);
            float2 vd = unpack2(acc2[i][3]);
            float4 o1, o2;
            o1.x = va.x+b2[c0];   o1.y = va.y+b2[c0+1];
            o1.z = vb.x+b2[c0+2]; o1.w = vb.y+b2[c0+3];
            o2.x = vc.x+b2[c0+4]; o2.y = vc.y+b2[c0+5];
            o2.z = vd.x+b2[c0+6]; o2.w = vd.y+b2[c0+7];
            *(float4*)(out + (size_t)row*128 + c0)     = o1;
            *(float4*)(out + (size_t)row*128 + c0 + 4) = o2;
        }
    }
}

// ==================== host ====================
// Confirmed layout: dict order with scalars at 10,11.
// Multi-stream fork-join (graph-capturable): pairtab chain || geom chain || bucketing.
extern "C" void kernel_launch(void* const* d_in, const int* in_sizes, int n_in,
                              void* d_out, int out_size){
    const float* h_flat = (const float*)d_in[0];
    const int*   z_flat = (const int*)d_in[1];
    const float* e_feat = (const float*)d_in[2];
    const int*   p_cen  = (const int*)d_in[3];
    const int*   p_j    = (const int*)d_in[4];
    const int*   p_k    = (const int*)d_in[5];
    const float* p_r0j  = (const float*)d_in[6];
    const float* p_r0k  = (const float*)d_in[7];
    const float* p_rjk  = (const float*)d_in[8];
    const float* p_cos  = (const float*)d_in[9];
    const float* z_emb  = (const float*)d_in[12];
    const float* peW1 = (const float*)d_in[13];
    const float* peb1 = (const float*)d_in[14];
    const float* peW2 = (const float*)d_in[15];
    const float* peb2 = (const float*)d_in[16];
    const float* peW3 = (const float*)d_in[17];
    const float* peb3 = (const float*)d_in[18];
    const float* gW1  = (const float*)d_in[19];
    const float* gb1  = (const float*)d_in[20];
    const float* gW2  = (const float*)d_in[21];
    const float* gb2  = (const float*)d_in[22];
    const float* gW3  = (const float*)d_in[23];
    const float* gb3  = (const float*)d_in[24];
    const float* oW1  = (const float*)d_in[25];
    const float* ob1  = (const float*)d_in[26];
    const float* oW2  = (const float*)d_in[27];
    const float* ob2  = (const float*)d_in[28];
    float* out = (float*)d_out;

    int P  = in_sizes[3];
    int bn = in_sizes[0] / AD;
    int nE = in_sizes[2] / 32;
    if (P > CAPP) P = CAPP;
    if (bn > BN) bn = BN;
    if (nE > NEE) nE = NEE;

    const int smem_geom = (32*96 + 2*32*H1S + 32)*4 + 64*4;   // 79232 B
    const int smem_out  = (64*36 + 64*260)*4;                 // 75776 B
    const int smem_pair = 2*64*132*4;                         // 67584 B
    cudaFuncSetAttribute(k_geom,    cudaFuncAttributeMaxDynamicSharedMemorySize, smem_geom);
    cudaFuncSetAttribute(k_outmlp,  cudaFuncAttributeMaxDynamicSharedMemorySize, smem_out);
    cudaFuncSetAttribute(k_pairtab, cudaFuncAttributeMaxDynamicSharedMemorySize, smem_pair);

    // Side streams + events, created once on the first (uncaptured correctness) call.
    static cudaStream_t s1 = 0, s2 = 0;
    static cudaEvent_t evRoot = 0, evGeom = 0, evPlace = 0;
    if (!s1){
        cudaStreamCreateWithFlags(&s1, cudaStreamNonBlocking);
        cudaStreamCreateWithFlags(&s2, cudaStreamNonBlocking);
        cudaEventCreateWithFlags(&evRoot,  cudaEventDisableTiming);
        cudaEventCreateWithFlags(&evGeom,  cudaEventDisableTiming);
        cudaEventCreateWithFlags(&evPlace, cudaEventDisableTiming);
    }

    // fork
    cudaEventRecord(evRoot, 0);
    cudaStreamWaitEvent(s1, evRoot, 0);
    cudaStreamWaitEvent(s2, evRoot, 0);

    // chain A (default stream): pe_layer1 -> pairtab (tf32 tensor core)
    k_pe_layer1<<<202 + nE, PH>>>(z_emb, e_feat, peW1, peb1);
    k_pairtab<<<TABROWS/64, 128, smem_pair>>>(peW2, peb2, peW3, peb3);

    // chain B (s1): hproj -> geom
    k_hproj<<<dim3(bn/8, 2), 256, 0, s1>>>(h_flat, gW1);
    k_geom<<<(P + 31)/32, 256, smem_geom, s1>>>(gW1, gb1, gW2, gb2, gW3, gb3,
                                                p_j, p_k, p_r0j, p_r0k, p_rjk, p_cos, P, bn);
    cudaEventRecord(evGeom, s1);

    // chain C (s2): zero -> count -> scan -> place
    k_zero<<<(BN + 255)/256, 256, 0, s2>>>();
    k_count<<<(P + 255)/256, 256, 0, s2>>>(p_cen, p_j, p_k, z_flat, P, bn);
    k_scan<<<1, BN, 0, s2>>>();
    k_place<<<(P + 255)/256, 256, 0, s2>>>(p_cen, P, bn);
    cudaEventRecord(evPlace, s2);

    // join into default stream
    cudaStreamWaitEvent(0, evGeom, 0);
    cudaStreamWaitEvent(0, evPlace, 0);

    k_agg<<<bn, 256>>>();
    k_outmlp<<<(bn*nE)/64, 256, smem_out>>>(oW1, ob1, oW2, ob2, out);
}